// round 13
// baseline (speedup 1.0000x reference)
#include <cuda_runtime.h>
#include <cuda_bf16.h>

#define BATCH 32
#define CIN   256
#define CC    64
#define PT    196     // 14*14
#define HT    14
#define PS    4096    // 64*64
#define HS    64
#define NGROUP 32     // groups of 2 channels
#define XSZ   5184    // conv3 floats per buffer: 8*18*36 == 9*8*72
#define CW    70      // corr tile width (64 + 6 halo)

typedef unsigned long long ull;

// ---------------- packed f32x2 / tf32 / cp.async helpers --------------------
__device__ __forceinline__ ull fma2(ull a, ull b, ull c) {
    ull d;
    asm("fma.rn.f32x2 %0, %1, %2, %3;" : "=l"(d) : "l"(a), "l"(b), "l"(c));
    return d;
}
__device__ __forceinline__ ull pack2(float lo, float hi) {
    ull d;
    asm("mov.b64 %0, {%1, %2};" : "=l"(d) : "f"(lo), "f"(hi));
    return d;
}
__device__ __forceinline__ float2 unpack2(ull v) {
    float2 r;
    asm("mov.b64 {%0, %1}, %2;" : "=f"(r.x), "=f"(r.y) : "l"(v));
    return r;
}
__device__ __forceinline__ float to_tf32(float v) {
    unsigned u;
    asm("cvt.rna.tf32.f32 %0, %1;" : "=r"(u) : "f"(v));
    return __uint_as_float(u);
}
__device__ __forceinline__ void mma_tf32(float* c, const unsigned* a,
                                         unsigned b0, unsigned b1) {
    asm("mma.sync.aligned.m16n8k8.row.col.f32.tf32.tf32.f32 "
        "{%0,%1,%2,%3}, {%4,%5,%6,%7}, {%8,%9}, {%0,%1,%2,%3};"
        : "+f"(c[0]), "+f"(c[1]), "+f"(c[2]), "+f"(c[3])
        : "r"(a[0]), "r"(a[1]), "r"(a[2]), "r"(a[3]), "r"(b0), "r"(b1));
}
__device__ __forceinline__ void cpa4(unsigned dst, const float* src) {
    asm volatile("cp.async.ca.shared.global [%0], [%1], 4;" :: "r"(dst), "l"(src));
}
__device__ __forceinline__ void cpa16(unsigned dst, const float* src) {
    asm volatile("cp.async.cg.shared.global [%0], [%1], 16;" :: "r"(dst), "l"(src));
}
__device__ __forceinline__ void cpa_commit() {
    asm volatile("cp.async.commit_group;");
}
template <int N>
__device__ __forceinline__ void cpa_wait() {
    asm volatile("cp.async.wait_group %0;" :: "n"(N));
}

// ---------------- scratch (device globals; allocation-free) ----------------
__device__ float g_sraw[(size_t)BATCH*CC*PS];   // raw search conv1x1 (pre-GN)
__device__ float g_corr[(size_t)BATCH*CC*PS];   // correlation (tf32-rounded)
__device__ float g_y   [(size_t)BATCH*CC*PS];   // conv3x3 output (pre-GN)
__device__ float g_tker[(size_t)BATCH*CC*49];   // pooled 7x7 template kernels
__device__ float g_tglob[(size_t)BATCH*CC];     // template global means
__device__ float g_wp1t[9*64*64];               // conv3 weights, tf32, [tap][ci][oc]
__device__ float g_wst [256*64];                // w_s, tf32, [k][oc]
__device__ float g_smean[BATCH*NGROUP];
__device__ float g_srstd[BATCH*NGROUP];
__device__ float g_pmean[BATCH*NGROUP];
__device__ float g_prstd[BATCH*NGROUP];
__device__ float2 g_p0[512*16*16];              // sgemm stats partials
__device__ float2 g_p1[256*32*16];              // conv3 stats partials

// ---------------- 0) weight prep: tf32 + transposes ------------------------
__global__ void k_wprep(const float* __restrict__ wp1, const float* __restrict__ ws) {
    int i = blockIdx.x * 1024 + threadIdx.x;
    if (i < 9 * 64 * 64) {
        int tap = i >> 12, rem = i & 4095;
        int ciG = rem >> 6, oc = rem & 63;
        g_wp1t[i] = to_tf32(wp1[oc * (CC * 9) + ciG * 9 + tap]);
    } else {
        int j = i - 9 * 64 * 64;
        if (j < 256 * 64) {
            int k = j >> 6, oc = j & 63;
            g_wst[j] = to_tf32(ws[oc * CIN + k]);
        }
    }
}

// ---------------- 1) template branch: conv1x1 + GN + relu + pools ----------
__global__ void k_template(const float* __restrict__ tf, const float* __restrict__ wt,
                           const float* __restrict__ gw, const float* __restrict__ gb) {
    int b = blockIdx.x, g = blockIdx.y;
    __shared__ float tv[392];
    __shared__ ull  wsm[256];            // (w[2g][ci], w[2g+1][ci])
    __shared__ float r1[128], r2[128];
    __shared__ float s_mean, s_rstd;
    int tid = threadIdx.x;
    const float* x = tf + (size_t)b * CIN * PT;

    for (int i = tid; i < 256; i += 128)
        wsm[i] = pack2(wt[(g * 2) * CIN + i], wt[(g * 2 + 1) * CIN + i]);
    __syncthreads();

    for (int p = tid; p < PT; p += 128) {
        ull acc = 0ull;
        #pragma unroll 4
        for (int ci = 0; ci < CIN; ci++) {
            float xv = x[ci * PT + p];
            acc = fma2(wsm[ci], pack2(xv, xv), acc);
        }
        float2 r = unpack2(acc);
        tv[p] = r.x; tv[PT + p] = r.y;
    }
    __syncthreads();

    float s = 0.f, ss = 0.f;
    for (int idx = tid; idx < 392; idx += 128) { float v = tv[idx]; s += v; ss += v * v; }
    r1[tid] = s; r2[tid] = ss;
    __syncthreads();
    for (int o = 64; o > 0; o >>= 1) {
        if (tid < o) { r1[tid] += r1[tid + o]; r2[tid] += r2[tid + o]; }
        __syncthreads();
    }
    if (tid == 0) {
        float m = r1[0] * (1.f / 392.f);
        float var = r2[0] * (1.f / 392.f) - m * m;
        s_mean = m; s_rstd = rsqrtf(var + 1e-5f);
    }
    __syncthreads();

    for (int idx = tid; idx < 392; idx += 128) {
        int c = idx / PT;
        float v = (tv[idx] - s_mean) * s_rstd * gw[g * 2 + c] + gb[g * 2 + c];
        tv[idx] = fmaxf(v, 0.f);
    }
    __syncthreads();

    if (tid < 98) {
        int c = tid / 49, cell = tid - c * 49;
        int i = cell / 7, j = cell - i * 7;
        int base = c * PT + (2 * i) * HT + 2 * j;
        float v = 0.25f * (tv[base] + tv[base + 1] + tv[base + HT] + tv[base + HT + 1]);
        g_tker[((size_t)b * CC + g * 2 + c) * 49 + cell] = v;
    }
    if (tid < 2) {
        float acc = 0.f;
        for (int p = 0; p < PT; p++) acc += tv[tid * PT + p];
        g_tglob[(size_t)b * CC + g * 2 + tid] = acc * (1.f / 196.f);
    }
}

// ---------------- 2) search conv1x1 GEMM, tf32 mma + cp.async pipeline -----
__global__ void __launch_bounds__(512) k_sgemm(const float* __restrict__ sf) {
    __shared__ float As[2][16 * 72];    // [k][oc], stride 72
    __shared__ float Bs[2][16 * 264];   // [k][px], stride 264
    int strip = blockIdx.x, b = blockIdx.y;
    int p0 = strip * 256;
    int tid = threadIdx.x;
    int w = tid >> 5, lane = tid & 31;
    int gid = lane >> 2, tig = lane & 3;
    int m = w & 3, ng = w >> 2;
    int m0 = m * 16;

    const float* xb = sf + (size_t)b * CIN * PS + p0;

    auto fill = [&](int k0, int t) {
        unsigned a_s = (unsigned)__cvta_generic_to_shared(As[t]);
        unsigned b_s = (unsigned)__cvta_generic_to_shared(Bs[t]);
        for (int i = tid; i < 256; i += 512) {
            int k = i >> 4, q = i & 15;
            cpa16(a_s + (unsigned)(k * 72 + q * 4) * 4,
                  g_wst + (k0 + k) * 64 + q * 4);
        }
        for (int i = tid; i < 1024; i += 512) {
            int k = i >> 6, p4 = i & 63;
            cpa16(b_s + (unsigned)(k * 264 + p4 * 4) * 4,
                  xb + (size_t)(k0 + k) * PS + p4 * 4);
        }
    };

    float acc[8][4];
    #pragma unroll
    for (int i = 0; i < 8; i++)
        #pragma unroll
        for (int j = 0; j < 4; j++) acc[i][j] = 0.f;

    fill(0, 0);
    cpa_commit();

    for (int c = 0; c < 16; c++) {
        if (c < 15) { fill((c + 1) * 16, (c + 1) & 1); cpa_commit(); }
        if (c < 15) cpa_wait<1>(); else cpa_wait<0>();
        __syncthreads();

        const float* Ab = As[c & 1];
        const float* Bb = Bs[c & 1];

        #pragma unroll
        for (int ks = 0; ks < 2; ks++) {
            int kb = 8 * ks;
            unsigned a[4];
            a[0] = __float_as_uint(Ab[(kb + tig) * 72 + m0 + gid]);
            a[1] = __float_as_uint(Ab[(kb + tig) * 72 + m0 + gid + 8]);
            a[2] = __float_as_uint(Ab[(kb + tig + 4) * 72 + m0 + gid]);
            a[3] = __float_as_uint(Ab[(kb + tig + 4) * 72 + m0 + gid + 8]);
            #pragma unroll
            for (int nt = 0; nt < 8; nt++) {
                int n0 = ng * 64 + nt * 8;
                unsigned b0 = __float_as_uint(Bb[(kb + tig) * 264 + n0 + gid]);
                unsigned b1 = __float_as_uint(Bb[(kb + tig + 4) * 264 + n0 + gid]);
                mma_tf32(acc[nt], a, b0, b1);
            }
        }
        __syncthreads();
    }

    float s0 = 0.f, ss0 = 0.f, s1 = 0.f, ss1 = 0.f;
    int oc0 = m0 + gid;
    #pragma unroll
    for (int nt = 0; nt < 8; nt++) {
        int n0 = ng * 64 + nt * 8;
        float c0 = acc[nt][0], c1 = acc[nt][1], c2 = acc[nt][2], c3 = acc[nt][3];
        size_t base = (size_t)p0 + n0 + 2 * tig;
        *(float2*)(g_sraw + ((size_t)b * CC + oc0) * PS + base)     = make_float2(c0, c1);
        *(float2*)(g_sraw + ((size_t)b * CC + oc0 + 8) * PS + base) = make_float2(c2, c3);
        s0 += c0 + c1; ss0 += c0 * c0 + c1 * c1;
        s1 += c2 + c3; ss1 += c2 * c2 + c3 * c3;
    }
    #pragma unroll
    for (int off = 2; off > 0; off >>= 1) {
        s0  += __shfl_down_sync(0xffffffffu, s0,  off, 4);
        ss0 += __shfl_down_sync(0xffffffffu, ss0, off, 4);
        s1  += __shfl_down_sync(0xffffffffu, s1,  off, 4);
        ss1 += __shfl_down_sync(0xffffffffu, ss1, off, 4);
    }
    if (tig == 0) {
        size_t pbase = ((size_t)strip * 32 + b) * 16 + w;
        g_p0[pbase * 16 + gid]     = make_float2(s0, ss0);
        g_p0[pbase * 16 + gid + 8] = make_float2(s1, ss1);
    }
}

// ---------------- 3) parallel reduce partials -> mean/rstd -----------------
__global__ void __launch_bounds__(256) k_red(int which) {
    int gidx = blockIdx.x * 256 + threadIdx.x;
    int out = gidx >> 5;
    int lane = gidx & 31;
    if (out >= 1024) return;
    int b = out >> 5, g = out & 31;
    const float2* part = which ? g_p1 : g_p0;
    int wdim = which ? 32 : 16;
    int ngi_bits = which ? 3 : 2;
    float s = 0.f, ss = 0.f;
    #pragma unroll
    for (int k = 0; k < 4; k++) {
        int t = lane + 32 * k;               // 0..127
        int cpair = t & 1, u = t >> 1;       // u 0..63
        int ngi = u & ((1 << ngi_bits) - 1);
        int tile = u >> ngi_bits;
        int oc = 2 * g + cpair, m = oc >> 4, rr = oc & 15;
        int w = ngi * 4 + m;
        float2 v = part[(((size_t)tile * 32 + b) * wdim + w) * 16 + rr];
        s += v.x; ss += v.y;
    }
    #pragma unroll
    for (int off = 16; off > 0; off >>= 1) {
        s  += __shfl_down_sync(0xffffffffu, s,  off);
        ss += __shfl_down_sync(0xffffffffu, ss, off);
    }
    if (lane == 0) {
        float m = s * (1.f / 8192.f);
        float var = ss * (1.f / 8192.f) - m * m;
        if (which) { g_pmean[out] = m; g_prstd[out] = rsqrtf(var + 1e-5f); }
        else       { g_smean[out] = m; g_srstd[out] = rsqrtf(var + 1e-5f); }
    }
}

// ---------------- 4) corr: overlapping-pair FFMA2 tile ---------------------
// grid (4 strips of 16x64, 64 ch, 32 batch), 128 threads, 8 px per thread.
// smp[i] = (v_i, v_{i+1}) -> every tap offset is one aligned LDS.64, zero packs.
__global__ void __launch_bounds__(128) k_corr(const float* __restrict__ gnw,
                                              const float* __restrict__ gnb) {
    int strip = blockIdx.x, c = blockIdx.y, b = blockIdx.z;
    int ty0 = strip * 16;
    __shared__ float sm[22 * CW];
    __shared__ ull  smp[22 * CW];
    __shared__ ull  kwd[49];
    int tid = threadIdx.x;
    int bg = b * NGROUP + (c >> 1);
    float mean = g_smean[bg], rstd = g_srstd[bg];
    float gamma = gnw[c], beta = gnb[c];
    float tg = g_tglob[(size_t)b * CC + c];
    const float* src = g_sraw + ((size_t)b * CC + c) * PS;

    // scalar tile: xx <-> gx = xx-3, rows ty0-3 .. ty0+18
    for (int i = tid; i < 22 * CW; i += 128) {
        int yy = i / CW, xx = i - yy * CW;
        int gy = ty0 + yy - 3, gx = xx - 3;
        float v = 0.f;
        if ((unsigned)gy < 64u && (unsigned)gx < 64u) {
            float r = src[gy * HS + gx];
            v = fmaxf((r - mean) * rstd * gamma + beta, 0.f);
        }
        sm[i] = v;
    }
    if (tid < 49) {
        float wv = g_tker[((size_t)b * CC + c) * 49 + tid];
        kwd[tid] = pack2(wv, wv);
    }
    __syncthreads();

    // overlapping pair tile
    for (int i = tid; i < 22 * CW - 1; i += 128)
        smp[i] = pack2(sm[i], sm[i + 1]);
    __syncthreads();

    int row = tid >> 3;            // out row 0..15
    int colb = (tid & 7) * 8;      // out col base (8 px: 4 pairs)
    ull acc[4] = {0ull, 0ull, 0ull, 0ull};

    #pragma unroll
    for (int ky = 0; ky < 7; ky++) {
        const ull* rp = &smp[(row + ky) * CW + colb];
        #pragma unroll
        for (int kx = 0; kx < 7; kx++) {
            ull wp = kwd[ky * 7 + kx];
            acc[0] = fma2(wp, rp[kx],     acc[0]);
            acc[1] = fma2(wp, rp[kx + 2], acc[1]);
            acc[2] = fma2(wp, rp[kx + 4], acc[2]);
            acc[3] = fma2(wp, rp[kx + 6], acc[3]);
        }
    }
    // global corr: center tap at xx = gx+3
    {
        ull tgp = pack2(tg, tg);
        const ull* rp = &smp[(row + 3) * CW + colb + 3];
        acc[0] = fma2(tgp, rp[0], acc[0]);
        acc[1] = fma2(tgp, rp[2], acc[1]);
        acc[2] = fma2(tgp, rp[4], acc[2]);
        acc[3] = fma2(tgp, rp[6], acc[3]);
    }

    float2 u0 = unpack2(acc[0]), u1 = unpack2(acc[1]);
    float2 u2 = unpack2(acc[2]), u3 = unpack2(acc[3]);
    float* dst = g_corr + ((size_t)b * CC + c) * PS + (ty0 + row) * HS + colb;
    *(float4*)dst = make_float4(to_tf32(u0.x), to_tf32(u0.y),
                                to_tf32(u1.x), to_tf32(u1.y));
    *(float4*)(dst + 4) = make_float4(to_tf32(u2.x), to_tf32(u2.y),
                                      to_tf32(u3.x), to_tf32(u3.y));
}

// ---------------- 5) conv3x3 mma.sync tf32, cp.async double-buffered -------
__global__ void __launch_bounds__(1024) k_conv3() {
    extern __shared__ float dyn[];
    int tile = blockIdx.x, b = blockIdx.y;
    int ty0 = (tile >> 1) * 16, tx0 = (tile & 1) * 32;
    int tid = threadIdx.x;
    int w = tid >> 5, lane = tid & 31;
    int gid = lane >> 2, tig = lane & 3;
    int m = w & 3, ng = w >> 2;
    int m0 = m * 16;
    int gxl = tx0 - 1;
    int gx0 = (tx0 == 0) ? 0 : gxl;

    for (int i = tid; i < 2 * XSZ; i += 1024) dyn[i] = 0.f;
    __syncthreads();

    auto fill = [&](int cc0, int t) {
        unsigned xs_s = (unsigned)__cvta_generic_to_shared(dyn + t * XSZ);
        unsigned ws_s = (unsigned)__cvta_generic_to_shared(dyn + 2 * XSZ + t * XSZ);
        for (int i = tid; i < 8 * 594; i += 1024) {
            int ci = i / 594, rem = i - ci * 594;
            int yy = rem / 33, j = rem - yy * 33;
            int gy = ty0 + yy - 1;
            if ((unsigned)gy < 64u) {
                int gx = gx0 + j;
                int xx = gx - gxl;
                cpa4(xs_s + (unsigned)(ci * 648 + yy * 36 + xx) * 4,
                     g_corr + ((size_t)b * CC + cc0 + ci) * PS + gy * HS + gx);
            }
        }
        for (int i = tid; i < 1152; i += 1024) {
            int tap = i >> 7, rem = i & 127;
            int ci = rem >> 4, q = rem & 15;
            cpa16(ws_s + (unsigned)(tap * 576 + ci * 72 + q * 4) * 4,
                  g_wp1t + (tap * 64 + cc0 + ci) * 64 + q * 4);
        }
    };

    float acc[8][4];
    #pragma unroll
    for (int i = 0; i < 8; i++)
        #pragma unroll
        for (int j = 0; j < 4; j++) acc[i][j] = 0.f;

    fill(0, 0);
    cpa_commit();

    for (int c = 0; c < 8; c++) {
        if (c < 7) { fill((c + 1) * 8, (c + 1) & 1); cpa_commit(); }
        if (c < 7) cpa_wait<1>(); else cpa_wait<0>();
        __syncthreads();

        const float* xsb = dyn + (c & 1) * XSZ;
        const float* wsb = dyn + 2 * XSZ + (c & 1) * XSZ;

        #pragma unroll
        for (int tap = 0; tap < 9; tap++) {
            int dy = tap / 3, dx = tap - 3 * (tap / 3);
            unsigned a[4];
            a[0] = __float_as_uint(wsb[tap * 576 + tig * 72 + m0 + gid]);
            a[1] = __float_as_uint(wsb[tap * 576 + tig * 72 + m0 + gid + 8]);
            a[2] = __float_as_uint(wsb[tap * 576 + (tig + 4) * 72 + m0 + gid]);
            a[3] = __float_as_uint(wsb[tap * 576 + (tig + 4) * 72 + m0 + gid + 8]);
            #pragma unroll
            for (int nt = 0; nt < 8; nt++) {
                int n0 = ng * 64 + nt * 8;
                int y0 = n0 >> 5, x0 = n0 & 31;
                unsigned b0 = __float_as_uint(
                    xsb[tig * 648 + (y0 + dy) * 36 + x0 + gid + dx]);
                unsigned b1 = __float_as_uint(
                    xsb[(tig + 4) * 648 + (y0 + dy) * 36 + x0 + gid + dx]);
                mma_tf32(acc[nt], a, b0, b1);
            }
        }
        __syncthreads();
    }

    float s0 = 0.f, ss0 = 0.f, s1 = 0.f, ss1 = 0.f;
    int oc0 = m0 + gid;
    #pragma unroll
    for (int nt = 0; nt < 8; nt++) {
        int n0 = ng * 64 + nt * 8;
        int y0 = n0 >> 5, x0 = n0 & 31;
        float c0 = acc[nt][0], c1 = acc[nt][1], c2 = acc[nt][2], c3 = acc[nt][3];
        size_t base = (size_t)(ty0 + y0) * HS + tx0 + x0 + 2 * tig;
        *(float2*)(g_y + ((size_t)b * CC + oc0) * PS + base)     = make_float2(c0, c1);
        *(float2*)(g_y + ((size_t)b * CC + oc0 + 8) * PS + base) = make_float2(c2, c3);
        s0 += c0 + c1; ss0 += c0 * c0 + c1 * c1;
        s1 += c2 + c3; ss1 += c2 * c2 + c3 * c3;
    }
    #pragma unroll
    for (int off = 2; off > 0; off >>= 1) {
        s0  += __shfl_down_sync(0xffffffffu, s0,  off, 4);
        ss0 += __shfl_down_sync(0xffffffffu, ss0, off, 4);
        s1  += __shfl_down_sync(0xffffffffu, s1,  off, 4);
        ss1 += __shfl_down_sync(0xffffffffu, ss1, off, 4);
    }
    if (tig == 0) {
        size_t pbase = ((size_t)tile * 32 + b) * 32 + w;
        g_p1[pbase * 16 + gid]     = make_float2(s0, ss0);
        g_p1[pbase * 16 + gid + 8] = make_float2(s1, ss1);
    }
}

// ---------------- 7) final: GN + relu + 1x1 conv, 1 px/thread --------------
__global__ void __launch_bounds__(128) k_final(const float* __restrict__ gnw,
                                               const float* __restrict__ gnb,
                                               const float* __restrict__ w2,
                                               const float* __restrict__ b2,
                                               float* __restrict__ out) {
    int idx = blockIdx.x * 128 + threadIdx.x;   // 131072 threads, 1 px each
    if (idx >= BATCH * PS) return;
    int b = idx >> 12, p = idx & (PS - 1);
    const float* yb = g_y + (size_t)b * CC * PS + p;
    float acc = b2[0];
    #pragma unroll 8
    for (int o = 0; o < CC; o++) {
        int bg = b * NGROUP + (o >> 1);
        float m = g_pmean[bg], rs = g_prstd[bg];
        float ga = gnw[o] * rs, be = gnb[o] - m * gnw[o] * rs;
        float v = yb[(size_t)o * PS];
        acc += w2[o] * fmaxf(v * ga + be, 0.f);
    }
    out[idx] = acc;
}

// ---------------- launch ----------------------------------------------------
extern "C" void kernel_launch(void* const* d_in, const int* in_sizes, int n_in,
                              void* d_out, int out_size) {
    const float* template_feat = (const float*)d_in[0];
    const float* search_feat   = (const float*)d_in[1];
    const float* w_t    = (const float*)d_in[2];
    const float* gn_t_w = (const float*)d_in[3];
    const float* gn_t_b = (const float*)d_in[4];
    const float* w_s    = (const float*)d_in[5];
    const float* gn_s_w = (const float*)d_in[6];
    const float* gn_s_b = (const float*)d_in[7];
    const float* w_p1   = (const float*)d_in[8];
    const float* gn_p_w = (const float*)d_in[9];
    const float* gn_p_b = (const float*)d_in[10];
    const float* w_p2   = (const float*)d_in[11];
    const float* b_p2   = (const float*)d_in[12];
    float* out = (float*)d_out;

    const int conv3_smem = 4 * XSZ * 4;   // 82944 B
    cudaFuncSetAttribute(k_conv3, cudaFuncAttributeMaxDynamicSharedMemorySize,
                         conv3_smem);

    k_wprep<<<52, 1024>>>(w_p1, w_s);
    k_template<<<dim3(BATCH, NGROUP), 128>>>(template_feat, w_t, gn_t_w, gn_t_b);
    k_sgemm<<<dim3(16, BATCH), 512>>>(search_feat);
    k_red<<<128, 256>>>(0);
    k_corr<<<dim3(4, CC, BATCH), 128>>>(gn_s_w, gn_s_b);
    k_conv3<<<dim3(8, BATCH), 1024, conv3_smem>>>();
    k_red<<<128, 256>>>(1);
    k_final<<<1024, 128>>>(gn_p_w, gn_p_b, w_p2, b_p2, out);
}

// round 14
// speedup vs baseline: 1.2299x; 1.2299x over previous
#include <cuda_runtime.h>
#include <cuda_bf16.h>

#define BATCH 32
#define CIN   256
#define CC    64
#define PT    196     // 14*14
#define HT    14
#define PS    4096    // 64*64
#define HS    64
#define NGROUP 32     // groups of 2 channels
#define XSZ   5184    // conv3 floats per buffer: 8*18*36 == 9*8*72

typedef unsigned long long ull;

// ---------------- packed f32x2 / tf32 / cp.async helpers --------------------
__device__ __forceinline__ ull fma2(ull a, ull b, ull c) {
    ull d;
    asm("fma.rn.f32x2 %0, %1, %2, %3;" : "=l"(d) : "l"(a), "l"(b), "l"(c));
    return d;
}
__device__ __forceinline__ ull pack2(float lo, float hi) {
    ull d;
    asm("mov.b64 %0, {%1, %2};" : "=l"(d) : "f"(lo), "f"(hi));
    return d;
}
__device__ __forceinline__ float2 unpack2(ull v) {
    float2 r;
    asm("mov.b64 {%0, %1}, %2;" : "=f"(r.x), "=f"(r.y) : "l"(v));
    return r;
}
__device__ __forceinline__ float to_tf32(float v) {
    unsigned u;
    asm("cvt.rna.tf32.f32 %0, %1;" : "=r"(u) : "f"(v));
    return __uint_as_float(u);
}
__device__ __forceinline__ void mma_tf32(float* c, const unsigned* a,
                                         unsigned b0, unsigned b1) {
    asm("mma.sync.aligned.m16n8k8.row.col.f32.tf32.tf32.f32 "
        "{%0,%1,%2,%3}, {%4,%5,%6,%7}, {%8,%9}, {%0,%1,%2,%3};"
        : "+f"(c[0]), "+f"(c[1]), "+f"(c[2]), "+f"(c[3])
        : "r"(a[0]), "r"(a[1]), "r"(a[2]), "r"(a[3]), "r"(b0), "r"(b1));
}
__device__ __forceinline__ void cpa4(unsigned dst, const float* src) {
    asm volatile("cp.async.ca.shared.global [%0], [%1], 4;" :: "r"(dst), "l"(src));
}
__device__ __forceinline__ void cpa16(unsigned dst, const float* src) {
    asm volatile("cp.async.cg.shared.global [%0], [%1], 16;" :: "r"(dst), "l"(src));
}
__device__ __forceinline__ void cpa_commit() {
    asm volatile("cp.async.commit_group;");
}
template <int N>
__device__ __forceinline__ void cpa_wait() {
    asm volatile("cp.async.wait_group %0;" :: "n"(N));
}

// ---------------- scratch (device globals; allocation-free) ----------------
__device__ float g_sraw[(size_t)BATCH*CC*PS];   // raw search conv1x1 (pre-GN)
__device__ float g_corr[(size_t)BATCH*CC*PS];   // correlation (tf32-rounded)
__device__ float g_y   [(size_t)BATCH*CC*PS];   // conv3x3 output (pre-GN)
__device__ float g_tker[(size_t)BATCH*CC*49];   // pooled 7x7 template kernels
__device__ float g_tglob[(size_t)BATCH*CC];     // template global means
__device__ float g_wp1t[9*64*64];               // conv3 weights, tf32, [tap][ci][oc]
__device__ float g_wst [256*64];                // w_s, tf32, [k][oc]
__device__ float g_smean[BATCH*NGROUP];
__device__ float g_srstd[BATCH*NGROUP];
__device__ float g_pmean[BATCH*NGROUP];
__device__ float g_prstd[BATCH*NGROUP];
__device__ float2 g_p0[512*16*16];              // sgemm stats partials
__device__ float2 g_p1[256*32*16];              // conv3 stats partials

// ---------------- 0) weight prep: tf32 + transposes ------------------------
__global__ void k_wprep(const float* __restrict__ wp1, const float* __restrict__ ws) {
    int i = blockIdx.x * 1024 + threadIdx.x;
    if (i < 9 * 64 * 64) {
        int tap = i >> 12, rem = i & 4095;
        int ciG = rem >> 6, oc = rem & 63;
        g_wp1t[i] = to_tf32(wp1[oc * (CC * 9) + ciG * 9 + tap]);
    } else {
        int j = i - 9 * 64 * 64;
        if (j < 256 * 64) {
            int k = j >> 6, oc = j & 63;
            g_wst[j] = to_tf32(ws[oc * CIN + k]);
        }
    }
}

// ---------------- 1) template branch: conv1x1 + GN + relu + pools ----------
__global__ void k_template(const float* __restrict__ tf, const float* __restrict__ wt,
                           const float* __restrict__ gw, const float* __restrict__ gb) {
    int b = blockIdx.x, g = blockIdx.y;
    __shared__ float tv[392];
    __shared__ ull  wsm[256];            // (w[2g][ci], w[2g+1][ci])
    __shared__ float r1[128], r2[128];
    __shared__ float s_mean, s_rstd;
    int tid = threadIdx.x;
    const float* x = tf + (size_t)b * CIN * PT;

    for (int i = tid; i < 256; i += 128)
        wsm[i] = pack2(wt[(g * 2) * CIN + i], wt[(g * 2 + 1) * CIN + i]);
    __syncthreads();

    for (int p = tid; p < PT; p += 128) {
        ull acc = 0ull;
        #pragma unroll 4
        for (int ci = 0; ci < CIN; ci++) {
            float xv = x[ci * PT + p];
            acc = fma2(wsm[ci], pack2(xv, xv), acc);
        }
        float2 r = unpack2(acc);
        tv[p] = r.x; tv[PT + p] = r.y;
    }
    __syncthreads();

    float s = 0.f, ss = 0.f;
    for (int idx = tid; idx < 392; idx += 128) { float v = tv[idx]; s += v; ss += v * v; }
    r1[tid] = s; r2[tid] = ss;
    __syncthreads();
    for (int o = 64; o > 0; o >>= 1) {
        if (tid < o) { r1[tid] += r1[tid + o]; r2[tid] += r2[tid + o]; }
        __syncthreads();
    }
    if (tid == 0) {
        float m = r1[0] * (1.f / 392.f);
        float var = r2[0] * (1.f / 392.f) - m * m;
        s_mean = m; s_rstd = rsqrtf(var + 1e-5f);
    }
    __syncthreads();

    for (int idx = tid; idx < 392; idx += 128) {
        int c = idx / PT;
        float v = (tv[idx] - s_mean) * s_rstd * gw[g * 2 + c] + gb[g * 2 + c];
        tv[idx] = fmaxf(v, 0.f);
    }
    __syncthreads();

    if (tid < 98) {
        int c = tid / 49, cell = tid - c * 49;
        int i = cell / 7, j = cell - i * 7;
        int base = c * PT + (2 * i) * HT + 2 * j;
        float v = 0.25f * (tv[base] + tv[base + 1] + tv[base + HT] + tv[base + HT + 1]);
        g_tker[((size_t)b * CC + g * 2 + c) * 49 + cell] = v;
    }
    if (tid < 2) {
        float acc = 0.f;
        for (int p = 0; p < PT; p++) acc += tv[tid * PT + p];
        g_tglob[(size_t)b * CC + g * 2 + tid] = acc * (1.f / 196.f);
    }
}

// ---------------- 2) search conv1x1 GEMM, tf32 mma + cp.async pipeline -----
__global__ void __launch_bounds__(512) k_sgemm(const float* __restrict__ sf) {
    __shared__ float As[2][16 * 72];    // [k][oc], stride 72
    __shared__ float Bs[2][16 * 264];   // [k][px], stride 264
    int strip = blockIdx.x, b = blockIdx.y;
    int p0 = strip * 256;
    int tid = threadIdx.x;
    int w = tid >> 5, lane = tid & 31;
    int gid = lane >> 2, tig = lane & 3;
    int m = w & 3, ng = w >> 2;
    int m0 = m * 16;

    const float* xb = sf + (size_t)b * CIN * PS + p0;

    auto fill = [&](int k0, int t) {
        unsigned a_s = (unsigned)__cvta_generic_to_shared(As[t]);
        unsigned b_s = (unsigned)__cvta_generic_to_shared(Bs[t]);
        for (int i = tid; i < 256; i += 512) {
            int k = i >> 4, q = i & 15;
            cpa16(a_s + (unsigned)(k * 72 + q * 4) * 4,
                  g_wst + (k0 + k) * 64 + q * 4);
        }
        for (int i = tid; i < 1024; i += 512) {
            int k = i >> 6, p4 = i & 63;
            cpa16(b_s + (unsigned)(k * 264 + p4 * 4) * 4,
                  xb + (size_t)(k0 + k) * PS + p4 * 4);
        }
    };

    float acc[8][4];
    #pragma unroll
    for (int i = 0; i < 8; i++)
        #pragma unroll
        for (int j = 0; j < 4; j++) acc[i][j] = 0.f;

    fill(0, 0);
    cpa_commit();

    for (int c = 0; c < 16; c++) {
        if (c < 15) { fill((c + 1) * 16, (c + 1) & 1); cpa_commit(); }
        if (c < 15) cpa_wait<1>(); else cpa_wait<0>();
        __syncthreads();

        const float* Ab = As[c & 1];
        const float* Bb = Bs[c & 1];

        #pragma unroll
        for (int ks = 0; ks < 2; ks++) {
            int kb = 8 * ks;
            unsigned a[4];
            a[0] = __float_as_uint(Ab[(kb + tig) * 72 + m0 + gid]);
            a[1] = __float_as_uint(Ab[(kb + tig) * 72 + m0 + gid + 8]);
            a[2] = __float_as_uint(Ab[(kb + tig + 4) * 72 + m0 + gid]);
            a[3] = __float_as_uint(Ab[(kb + tig + 4) * 72 + m0 + gid + 8]);
            #pragma unroll
            for (int nt = 0; nt < 8; nt++) {
                int n0 = ng * 64 + nt * 8;
                unsigned b0 = __float_as_uint(Bb[(kb + tig) * 264 + n0 + gid]);
                unsigned b1 = __float_as_uint(Bb[(kb + tig + 4) * 264 + n0 + gid]);
                mma_tf32(acc[nt], a, b0, b1);
            }
        }
        __syncthreads();
    }

    float s0 = 0.f, ss0 = 0.f, s1 = 0.f, ss1 = 0.f;
    int oc0 = m0 + gid;
    #pragma unroll
    for (int nt = 0; nt < 8; nt++) {
        int n0 = ng * 64 + nt * 8;
        float c0 = acc[nt][0], c1 = acc[nt][1], c2 = acc[nt][2], c3 = acc[nt][3];
        size_t base = (size_t)p0 + n0 + 2 * tig;
        *(float2*)(g_sraw + ((size_t)b * CC + oc0) * PS + base)     = make_float2(c0, c1);
        *(float2*)(g_sraw + ((size_t)b * CC + oc0 + 8) * PS + base) = make_float2(c2, c3);
        s0 += c0 + c1; ss0 += c0 * c0 + c1 * c1;
        s1 += c2 + c3; ss1 += c2 * c2 + c3 * c3;
    }
    #pragma unroll
    for (int off = 2; off > 0; off >>= 1) {
        s0  += __shfl_down_sync(0xffffffffu, s0,  off, 4);
        ss0 += __shfl_down_sync(0xffffffffu, ss0, off, 4);
        s1  += __shfl_down_sync(0xffffffffu, s1,  off, 4);
        ss1 += __shfl_down_sync(0xffffffffu, ss1, off, 4);
    }
    if (tig == 0) {
        size_t pbase = ((size_t)strip * 32 + b) * 16 + w;
        g_p0[pbase * 16 + gid]     = make_float2(s0, ss0);
        g_p0[pbase * 16 + gid + 8] = make_float2(s1, ss1);
    }
}

// ---------------- 3) parallel reduce partials -> mean/rstd -----------------
__global__ void __launch_bounds__(256) k_red(int which) {
    int gidx = blockIdx.x * 256 + threadIdx.x;
    int out = gidx >> 5;
    int lane = gidx & 31;
    if (out >= 1024) return;
    int b = out >> 5, g = out & 31;
    const float2* part = which ? g_p1 : g_p0;
    int wdim = which ? 32 : 16;
    int ngi_bits = which ? 3 : 2;
    float s = 0.f, ss = 0.f;
    #pragma unroll
    for (int k = 0; k < 4; k++) {
        int t = lane + 32 * k;               // 0..127
        int cpair = t & 1, u = t >> 1;       // u 0..63
        int ngi = u & ((1 << ngi_bits) - 1);
        int tile = u >> ngi_bits;
        int oc = 2 * g + cpair, m = oc >> 4, rr = oc & 15;
        int w = ngi * 4 + m;
        float2 v = part[(((size_t)tile * 32 + b) * wdim + w) * 16 + rr];
        s += v.x; ss += v.y;
    }
    #pragma unroll
    for (int off = 16; off > 0; off >>= 1) {
        s  += __shfl_down_sync(0xffffffffu, s,  off);
        ss += __shfl_down_sync(0xffffffffu, ss, off);
    }
    if (lane == 0) {
        float m = s * (1.f / 8192.f);
        float var = ss * (1.f / 8192.f) - m * m;
        if (which) { g_pmean[out] = m; g_prstd[out] = rsqrtf(var + 1e-5f); }
        else       { g_smean[out] = m; g_srstd[out] = rsqrtf(var + 1e-5f); }
    }
}

// ---------------- 4) corr = global + 7x7 depthwise local (scalar, proven) --
__global__ void __launch_bounds__(256) k_corr(const float* __restrict__ gnw,
                                              const float* __restrict__ gnb) {
    int tile = blockIdx.x, c = blockIdx.y, b = blockIdx.z;
    int ty0 = (tile >> 1) * 32, tx0 = (tile & 1) * 32;
    __shared__ float sm[38 * 38];
    __shared__ float kw[49];
    int tid = threadIdx.x;
    int bg = b * NGROUP + (c >> 1);
    float mean = g_smean[bg], rstd = g_srstd[bg];
    float gamma = gnw[c], beta = gnb[c];
    float tg = g_tglob[(size_t)b * CC + c];
    const float* src = g_sraw + ((size_t)b * CC + c) * PS;

    for (int i = tid; i < 38 * 38; i += 256) {
        int yy = i / 38, xx = i - yy * 38;
        int gy = ty0 + yy - 3, gx = tx0 + xx - 3;
        float v = 0.f;
        if ((unsigned)gy < 64u && (unsigned)gx < 64u) {
            float r = src[gy * HS + gx];
            v = fmaxf((r - mean) * rstd * gamma + beta, 0.f);
        }
        sm[i] = v;
    }
    if (tid < 49) kw[tid] = g_tker[((size_t)b * CC + c) * 49 + tid];
    __syncthreads();

    int p = tid * 4;
    int py = p >> 5, px = p & 31;
    float a0 = 0.f, a1 = 0.f, a2 = 0.f, a3 = 0.f;
    #pragma unroll
    for (int ky = 0; ky < 7; ky++) {
        const float* row = &sm[(py + ky) * 38 + px];
        #pragma unroll
        for (int kx = 0; kx < 7; kx++) {
            float w = kw[ky * 7 + kx];
            a0 += w * row[kx];
            a1 += w * row[kx + 1];
            a2 += w * row[kx + 2];
            a3 += w * row[kx + 3];
        }
    }
    const float* ctr = &sm[(py + 3) * 38 + px + 3];
    a0 += tg * ctr[0]; a1 += tg * ctr[1]; a2 += tg * ctr[2]; a3 += tg * ctr[3];

    float* dst = g_corr + ((size_t)b * CC + c) * PS + (ty0 + py) * HS + tx0 + px;
    *(float4*)dst = make_float4(to_tf32(a0), to_tf32(a1), to_tf32(a2), to_tf32(a3));
}

// ---------------- 5) conv3x3 mma.sync tf32, cp.async double-buffered -------
__global__ void __launch_bounds__(1024) k_conv3() {
    extern __shared__ float dyn[];
    int tile = blockIdx.x, b = blockIdx.y;
    int ty0 = (tile >> 1) * 16, tx0 = (tile & 1) * 32;
    int tid = threadIdx.x;
    int w = tid >> 5, lane = tid & 31;
    int gid = lane >> 2, tig = lane & 3;
    int m = w & 3, ng = w >> 2;
    int m0 = m * 16;
    int gxl = tx0 - 1;
    int gx0 = (tx0 == 0) ? 0 : gxl;

    for (int i = tid; i < 2 * XSZ; i += 1024) dyn[i] = 0.f;
    __syncthreads();

    auto fill = [&](int cc0, int t) {
        unsigned xs_s = (unsigned)__cvta_generic_to_shared(dyn + t * XSZ);
        unsigned ws_s = (unsigned)__cvta_generic_to_shared(dyn + 2 * XSZ + t * XSZ);
        for (int i = tid; i < 8 * 594; i += 1024) {
            int ci = i / 594, rem = i - ci * 594;
            int yy = rem / 33, j = rem - yy * 33;
            int gy = ty0 + yy - 1;
            if ((unsigned)gy < 64u) {
                int gx = gx0 + j;
                int xx = gx - gxl;
                cpa4(xs_s + (unsigned)(ci * 648 + yy * 36 + xx) * 4,
                     g_corr + ((size_t)b * CC + cc0 + ci) * PS + gy * HS + gx);
            }
        }
        for (int i = tid; i < 1152; i += 1024) {
            int tap = i >> 7, rem = i & 127;
            int ci = rem >> 4, q = rem & 15;
            cpa16(ws_s + (unsigned)(tap * 576 + ci * 72 + q * 4) * 4,
                  g_wp1t + (tap * 64 + cc0 + ci) * 64 + q * 4);
        }
    };

    float acc[8][4];
    #pragma unroll
    for (int i = 0; i < 8; i++)
        #pragma unroll
        for (int j = 0; j < 4; j++) acc[i][j] = 0.f;

    fill(0, 0);
    cpa_commit();

    for (int c = 0; c < 8; c++) {
        if (c < 7) { fill((c + 1) * 8, (c + 1) & 1); cpa_commit(); }
        if (c < 7) cpa_wait<1>(); else cpa_wait<0>();
        __syncthreads();

        const float* xsb = dyn + (c & 1) * XSZ;
        const float* wsb = dyn + 2 * XSZ + (c & 1) * XSZ;

        #pragma unroll
        for (int tap = 0; tap < 9; tap++) {
            int dy = tap / 3, dx = tap - 3 * (tap / 3);
            unsigned a[4];
            a[0] = __float_as_uint(wsb[tap * 576 + tig * 72 + m0 + gid]);
            a[1] = __float_as_uint(wsb[tap * 576 + tig * 72 + m0 + gid + 8]);
            a[2] = __float_as_uint(wsb[tap * 576 + (tig + 4) * 72 + m0 + gid]);
            a[3] = __float_as_uint(wsb[tap * 576 + (tig + 4) * 72 + m0 + gid + 8]);
            #pragma unroll
            for (int nt = 0; nt < 8; nt++) {
                int n0 = ng * 64 + nt * 8;
                int y0 = n0 >> 5, x0 = n0 & 31;
                unsigned b0 = __float_as_uint(
                    xsb[tig * 648 + (y0 + dy) * 36 + x0 + gid + dx]);
                unsigned b1 = __float_as_uint(
                    xsb[(tig + 4) * 648 + (y0 + dy) * 36 + x0 + gid + dx]);
                mma_tf32(acc[nt], a, b0, b1);
            }
        }
        __syncthreads();
    }

    float s0 = 0.f, ss0 = 0.f, s1 = 0.f, ss1 = 0.f;
    int oc0 = m0 + gid;
    #pragma unroll
    for (int nt = 0; nt < 8; nt++) {
        int n0 = ng * 64 + nt * 8;
        int y0 = n0 >> 5, x0 = n0 & 31;
        float c0 = acc[nt][0], c1 = acc[nt][1], c2 = acc[nt][2], c3 = acc[nt][3];
        size_t base = (size_t)(ty0 + y0) * HS + tx0 + x0 + 2 * tig;
        *(float2*)(g_y + ((size_t)b * CC + oc0) * PS + base)     = make_float2(c0, c1);
        *(float2*)(g_y + ((size_t)b * CC + oc0 + 8) * PS + base) = make_float2(c2, c3);
        s0 += c0 + c1; ss0 += c0 * c0 + c1 * c1;
        s1 += c2 + c3; ss1 += c2 * c2 + c3 * c3;
    }
    #pragma unroll
    for (int off = 2; off > 0; off >>= 1) {
        s0  += __shfl_down_sync(0xffffffffu, s0,  off, 4);
        ss0 += __shfl_down_sync(0xffffffffu, ss0, off, 4);
        s1  += __shfl_down_sync(0xffffffffu, s1,  off, 4);
        ss1 += __shfl_down_sync(0xffffffffu, ss1, off, 4);
    }
    if (tig == 0) {
        size_t pbase = ((size_t)tile * 32 + b) * 32 + w;
        g_p1[pbase * 16 + gid]     = make_float2(s0, ss0);
        g_p1[pbase * 16 + gid + 8] = make_float2(s1, ss1);
    }
}

// ---------------- 7) final: GN + relu + 1x1 conv, 2 px/thread --------------
__global__ void __launch_bounds__(128) k_final(const float* __restrict__ gnw,
                                               const float* __restrict__ gnb,
                                               const float* __restrict__ w2,
                                               const float* __restrict__ b2,
                                               float* __restrict__ out) {
    int idx = blockIdx.x * 128 + threadIdx.x;   // 65536 threads, 2 px each
    if (idx >= BATCH * PS / 2) return;
    int b = idx >> 11, p2 = idx & 2047;
    const float2* yb = (const float2*)(g_y + (size_t)b * CC * PS) + p2;
    float bias = b2[0];
    float2 acc = make_float2(bias, bias);
    #pragma unroll 8
    for (int o = 0; o < CC; o++) {
        int bg = b * NGROUP + (o >> 1);
        float m = g_pmean[bg], rs = g_prstd[bg];
        float ga = gnw[o] * rs, be = gnb[o] - m * gnw[o] * rs;
        float wv = w2[o];
        float2 v = yb[(size_t)o * (PS / 2)];
        acc.x += wv * fmaxf(v.x * ga + be, 0.f);
        acc.y += wv * fmaxf(v.y * ga + be, 0.f);
    }
    ((float2*)out)[idx] = acc;
}

// ---------------- launch ----------------------------------------------------
extern "C" void kernel_launch(void* const* d_in, const int* in_sizes, int n_in,
                              void* d_out, int out_size) {
    const float* template_feat = (const float*)d_in[0];
    const float* search_feat   = (const float*)d_in[1];
    const float* w_t    = (const float*)d_in[2];
    const float* gn_t_w = (const float*)d_in[3];
    const float* gn_t_b = (const float*)d_in[4];
    const float* w_s    = (const float*)d_in[5];
    const float* gn_s_w = (const float*)d_in[6];
    const float* gn_s_b = (const float*)d_in[7];
    const float* w_p1   = (const float*)d_in[8];
    const float* gn_p_w = (const float*)d_in[9];
    const float* gn_p_b = (const float*)d_in[10];
    const float* w_p2   = (const float*)d_in[11];
    const float* b_p2   = (const float*)d_in[12];
    float* out = (float*)d_out;

    const int conv3_smem = 4 * XSZ * 4;   // 82944 B
    cudaFuncSetAttribute(k_conv3, cudaFuncAttributeMaxDynamicSharedMemorySize,
                         conv3_smem);

    k_wprep<<<52, 1024>>>(w_p1, w_s);
    k_template<<<dim3(BATCH, NGROUP), 128>>>(template_feat, w_t, gn_t_w, gn_t_b);
    k_sgemm<<<dim3(16, BATCH), 512>>>(search_feat);
    k_red<<<128, 256>>>(0);
    k_corr<<<dim3(4, CC, BATCH), 256>>>(gn_s_w, gn_s_b);
    k_conv3<<<dim3(8, BATCH), 1024, conv3_smem>>>();
    k_red<<<128, 256>>>(1);
    k_final<<<512, 128>>>(gn_p_w, gn_p_b, w_p2, b_p2, out);
}